// round 1
// baseline (speedup 1.0000x reference)
#include <cuda_runtime.h>

#define BS   2
#define H    16
#define QLEN 1024
#define SLEN 1024
#define DK   64
#define ROWS 4          // q rows per block
#define T    128        // threads per block

#define O_ELEMS  (BS*H*QLEN*DK)          // 2097152
#define W_ELEMS  (BS*H*QLEN*SLEN)        // 33554432
#define FULL_OUT (O_ELEMS + 2*W_ELEMS)   // 69206016

__global__ __launch_bounds__(T)
void sdpa_kernel(const float* __restrict__ q,
                 const float* __restrict__ k,
                 const float* __restrict__ v,
                 const float* __restrict__ prev,
                 const float* __restrict__ scale_p,
                 float* __restrict__ out_o,
                 float* __restrict__ out_w,
                 float* __restrict__ out_s)
{
    __shared__ float q_s[ROWS][DK];            // 1 KB
    __shared__ float w_s[ROWS][SLEN];          // 16 KB
    __shared__ float part[8][ROWS][DK];        // 8 KB

    const int tid  = threadIdx.x;
    const int blk  = blockIdx.x;
    const int bh   = blk / (QLEN / ROWS);          // 0..31
    const int q0   = (blk % (QLEN / ROWS)) * ROWS; // 0..1020 step 4

    const float scale = *scale_p;

    const float* qb = q    + ((size_t)bh * QLEN + q0) * DK;
    const float* kb = k    + (size_t)bh * DK * SLEN;
    const float* vb = v    + (size_t)bh * SLEN * DK;
    const float* pb = prev + ((size_t)bh * QLEN + q0) * SLEN;

    // ---- load q rows into smem ----
    for (int i = tid; i < ROWS * DK; i += T)
        q_s[i / DK][i % DK] = qb[i];
    __syncthreads();

    // ---- phase 1: scores = (q @ k) * scale + prev ----
    // 2 passes x (128 threads * 4 s) = 1024 s columns
    #pragma unroll
    for (int pass = 0; pass < 2; pass++) {
        const int s0 = pass * 512 + tid * 4;
        float4 acc[ROWS];
        #pragma unroll
        for (int r = 0; r < ROWS; r++) acc[r] = make_float4(0.f, 0.f, 0.f, 0.f);

        #pragma unroll 16
        for (int d = 0; d < DK; d++) {
            const float4 kv = *(const float4*)(kb + (size_t)d * SLEN + s0);
            #pragma unroll
            for (int r = 0; r < ROWS; r++) {
                const float qd = q_s[r][d];
                acc[r].x = fmaf(qd, kv.x, acc[r].x);
                acc[r].y = fmaf(qd, kv.y, acc[r].y);
                acc[r].z = fmaf(qd, kv.z, acc[r].z);
                acc[r].w = fmaf(qd, kv.w, acc[r].w);
            }
        }
        #pragma unroll
        for (int r = 0; r < ROWS; r++) {
            const float4 pv = *(const float4*)(pb + (size_t)r * SLEN + s0);
            float4 sc;
            sc.x = fmaf(acc[r].x, scale, pv.x);
            sc.y = fmaf(acc[r].y, scale, pv.y);
            sc.z = fmaf(acc[r].z, scale, pv.z);
            sc.w = fmaf(acc[r].w, scale, pv.w);
            *(float4*)&w_s[r][s0] = sc;
            if (out_s)
                *(float4*)(out_s + ((size_t)bh * QLEN + q0 + r) * SLEN + s0) = sc;
        }
    }
    __syncthreads();

    // ---- phase 2: softmax, one warp per row (shuffle-only reductions) ----
    {
        const int warp = tid >> 5;
        const int lane = tid & 31;
        const int r = warp;   // 4 warps == ROWS rows

        float mx = -1e30f;
        for (int i = lane; i < SLEN; i += 32)
            mx = fmaxf(mx, w_s[r][i]);
        #pragma unroll
        for (int o = 16; o > 0; o >>= 1)
            mx = fmaxf(mx, __shfl_xor_sync(0xffffffffu, mx, o));

        float sum = 0.f;
        for (int i = lane; i < SLEN; i += 32) {
            const float e = __expf(w_s[r][i] - mx);
            w_s[r][i] = e;
            sum += e;
        }
        #pragma unroll
        for (int o = 16; o > 0; o >>= 1)
            sum += __shfl_xor_sync(0xffffffffu, sum, o);

        const float inv = 1.0f / sum;
        float* wrow = out_w ? (out_w + ((size_t)bh * QLEN + q0 + r) * SLEN) : nullptr;
        for (int i = lane; i < SLEN; i += 32) {
            const float wv = w_s[r][i] * inv;
            w_s[r][i] = wv;
            if (wrow) wrow[i] = wv;     // contiguous 128B per warp-iter: coalesced
        }
    }
    __syncthreads();

    // ---- phase 3: output = weights @ v ----
    // 16 threads cover DK via float4 (d = (tid&15)*4), 8 s-partitions (g = tid>>4)
    {
        const int dg = (tid & 15) * 4;
        const int g  = tid >> 4;
        float4 acc[ROWS];
        #pragma unroll
        for (int r = 0; r < ROWS; r++) acc[r] = make_float4(0.f, 0.f, 0.f, 0.f);

        const int sBeg = g * (SLEN / 8);
        #pragma unroll 8
        for (int s = sBeg; s < sBeg + (SLEN / 8); s++) {
            const float4 vv = *(const float4*)(vb + (size_t)s * DK + dg);
            #pragma unroll
            for (int r = 0; r < ROWS; r++) {
                const float wv = w_s[r][s];   // broadcast across 16-thread group
                acc[r].x = fmaf(wv, vv.x, acc[r].x);
                acc[r].y = fmaf(wv, vv.y, acc[r].y);
                acc[r].z = fmaf(wv, vv.z, acc[r].z);
                acc[r].w = fmaf(wv, vv.w, acc[r].w);
            }
        }
        #pragma unroll
        for (int r = 0; r < ROWS; r++)
            *(float4*)&part[g][r][dg] = acc[r];
    }
    __syncthreads();

    // tree-reduce the 8 partials, write output (coalesced)
    for (int i = tid; i < ROWS * DK; i += T) {
        const int r = i / DK;
        const int d = i % DK;
        float s = 0.f;
        #pragma unroll
        for (int g = 0; g < 8; g++) s += part[g][r][d];
        out_o[((size_t)bh * QLEN + q0 + r) * DK + d] = s;
    }
}

extern "C" void kernel_launch(void* const* d_in, const int* in_sizes, int n_in,
                              void* d_out, int out_size)
{
    const float* q     = (const float*)d_in[0];
    const float* k     = (const float*)d_in[1];
    const float* v     = (const float*)d_in[2];
    const float* prev  = (const float*)d_in[3];
    const float* scale = (const float*)d_in[4];

    float* out_o = (float*)d_out;
    float* out_w = nullptr;
    float* out_s = nullptr;
    if (out_size >= FULL_OUT) {           // (output, attn_weights, attn_scores)
        out_w = out_o + O_ELEMS;
        out_s = out_w + W_ELEMS;
    }

    const int grid = BS * H * (QLEN / ROWS);   // 8192
    sdpa_kernel<<<grid, T>>>(q, k, v, prev, scale, out_o, out_w, out_s);
}

// round 2
// speedup vs baseline: 1.1081x; 1.1081x over previous
#include <cuda_runtime.h>

#define BS   2
#define H    16
#define QLEN 1024
#define SLEN 1024
#define DK   64
#define ROWS 8          // q rows per block
#define T    128        // threads per block
#define NGRP 8          // s-partitions in phase 3

#define O_ELEMS  (BS*H*QLEN*DK)          // 2097152
#define W_ELEMS  (BS*H*QLEN*SLEN)        // 33554432
#define FULL_OUT (O_ELEMS + 2*W_ELEMS)   // 69206016

// Blackwell packed fp32 FMA: one instruction, two lane-FMAs.
__device__ __forceinline__ float2 ffma2(float2 a, float2 b, float2 c)
{
    union { float2 f; unsigned long long u; } A, B, C, D;
    A.f = a; B.f = b; C.f = c;
    asm("fma.rn.f32x2 %0, %1, %2, %3;" : "=l"(D.u) : "l"(A.u), "l"(B.u), "l"(C.u));
    return D.f;
}

__global__ __launch_bounds__(T)
void sdpa_kernel(const float* __restrict__ q,
                 const float* __restrict__ k,
                 const float* __restrict__ v,
                 const float* __restrict__ prev,
                 const float* __restrict__ scale_p,
                 float* __restrict__ out_o,
                 float* __restrict__ out_w,
                 float* __restrict__ out_s)
{
    // q2 (phase 1 only) unioned with part (phase 3 only): 16KB
    __shared__ union {
        float2 q2[ROWS][DK];                 // duplicated q: (qd,qd) pairs, 4KB
        float  part[NGRP][ROWS][DK];         // phase-3 partials, 16KB
    } u;
    __shared__ float w_s[ROWS][SLEN];        // 32KB  -> total 48KB static

    const int tid  = threadIdx.x;
    const int blk  = blockIdx.x;
    const int bh   = blk / (QLEN / ROWS);          // 0..31
    const int q0   = (blk % (QLEN / ROWS)) * ROWS; // step 8

    const float scale = *scale_p;
    const float2 scale2 = make_float2(scale, scale);

    const float* qb = q    + ((size_t)bh * QLEN + q0) * DK;
    const float* kb = k    + (size_t)bh * DK * SLEN;
    const float* vb = v    + (size_t)bh * SLEN * DK;
    const float* pb = prev + ((size_t)bh * QLEN + q0) * SLEN;

    // ---- load q rows into smem, duplicated into f32x2 lanes ----
    for (int i = tid; i < ROWS * DK; i += T) {
        const float val = qb[i];
        u.q2[i / DK][i % DK] = make_float2(val, val);
    }
    __syncthreads();

    // ---- phase 1: scores = (q @ k) * scale + prev ----
    // 2 passes x (128 threads * 4 s-columns) = 1024 columns
    #pragma unroll
    for (int pass = 0; pass < 2; pass++) {
        const int s0 = pass * 512 + tid * 4;
        float2 accA[ROWS], accB[ROWS];       // (x,y) and (z,w) lane pairs
        #pragma unroll
        for (int r = 0; r < ROWS; r++) {
            accA[r] = make_float2(0.f, 0.f);
            accB[r] = make_float2(0.f, 0.f);
        }

        #pragma unroll 8
        for (int d = 0; d < DK; d++) {
            const float4 kv = *(const float4*)(kb + (size_t)d * SLEN + s0);
            const float2 kA = make_float2(kv.x, kv.y);
            const float2 kB = make_float2(kv.z, kv.w);
            #pragma unroll
            for (int r = 0; r < ROWS; r++) {
                const float2 q2 = u.q2[r][d];    // LDS.64 broadcast
                accA[r] = ffma2(q2, kA, accA[r]);
                accB[r] = ffma2(q2, kB, accB[r]);
            }
        }
        #pragma unroll
        for (int r = 0; r < ROWS; r++) {
            const float4 pv = __ldcs((const float4*)(pb + (size_t)r * SLEN + s0));
            const float2 sA = ffma2(accA[r], scale2, make_float2(pv.x, pv.y));
            const float2 sB = ffma2(accB[r], scale2, make_float2(pv.z, pv.w));
            float4 sc; sc.x = sA.x; sc.y = sA.y; sc.z = sB.x; sc.w = sB.y;
            *(float4*)&w_s[r][s0] = sc;
            if (out_s)
                __stcs((float4*)(out_s + ((size_t)bh * QLEN + q0 + r) * SLEN + s0), sc);
        }
    }
    __syncthreads();

    // ---- phase 2: softmax, each warp handles 2 rows ----
    {
        const int warp = tid >> 5;
        const int lane = tid & 31;
        #pragma unroll
        for (int rr = 0; rr < 2; rr++) {
            const int r = warp * 2 + rr;

            float mx = -1e30f;
            for (int i = lane; i < SLEN; i += 32)
                mx = fmaxf(mx, w_s[r][i]);
            #pragma unroll
            for (int o = 16; o > 0; o >>= 1)
                mx = fmaxf(mx, __shfl_xor_sync(0xffffffffu, mx, o));

            float sum = 0.f;
            for (int i = lane; i < SLEN; i += 32) {
                const float e = __expf(w_s[r][i] - mx);
                w_s[r][i] = e;
                sum += e;
            }
            #pragma unroll
            for (int o = 16; o > 0; o >>= 1)
                sum += __shfl_xor_sync(0xffffffffu, sum, o);

            const float inv = 1.0f / sum;
            float* wrow = out_w ? (out_w + ((size_t)bh * QLEN + q0 + r) * SLEN) : nullptr;
            for (int i = lane; i < SLEN; i += 32) {
                const float wv = w_s[r][i] * inv;
                w_s[r][i] = wv;
                if (wrow) __stcs(wrow + i, wv);
            }
        }
    }
    __syncthreads();

    // ---- phase 3: output = weights @ v, s-pair packed FMAs ----
    // 16 threads cover DK via float4 (dg), NGRP=8 s-partitions (g),
    // f32x2 lanes hold (even-s partial, odd-s partial).
    {
        const int dg = (tid & 15) * 4;
        const int g  = tid >> 4;
        float2 ax[ROWS], ay[ROWS], az[ROWS], aw[ROWS];
        #pragma unroll
        for (int r = 0; r < ROWS; r++) {
            ax[r] = make_float2(0.f, 0.f); ay[r] = make_float2(0.f, 0.f);
            az[r] = make_float2(0.f, 0.f); aw[r] = make_float2(0.f, 0.f);
        }

        const int sBeg = g * (SLEN / NGRP);
        #pragma unroll 4
        for (int sp = 0; sp < (SLEN / NGRP) / 2; sp++) {
            const int s = sBeg + sp * 2;
            const float4 v0 = *(const float4*)(vb + (size_t)s       * DK + dg);
            const float4 v1 = *(const float4*)(vb + (size_t)(s + 1) * DK + dg);
            const float2 px = make_float2(v0.x, v1.x);
            const float2 py = make_float2(v0.y, v1.y);
            const float2 pz = make_float2(v0.z, v1.z);
            const float2 pw = make_float2(v0.w, v1.w);
            #pragma unroll
            for (int r = 0; r < ROWS; r++) {
                const float2 w2 = *(const float2*)&w_s[r][s];  // LDS.64 broadcast
                ax[r] = ffma2(w2, px, ax[r]);
                ay[r] = ffma2(w2, py, ay[r]);
                az[r] = ffma2(w2, pz, az[r]);
                aw[r] = ffma2(w2, pw, aw[r]);
            }
        }
        #pragma unroll
        for (int r = 0; r < ROWS; r++) {
            float4 res;
            res.x = ax[r].x + ax[r].y;
            res.y = ay[r].x + ay[r].y;
            res.z = az[r].x + az[r].y;
            res.w = aw[r].x + aw[r].y;
            *(float4*)&u.part[g][r][dg] = res;
        }
    }
    __syncthreads();

    // tree-reduce the NGRP partials, write output (coalesced)
    for (int i = tid; i < ROWS * DK; i += T) {
        const int r = i / DK;
        const int d = i % DK;
        float s = 0.f;
        #pragma unroll
        for (int g = 0; g < NGRP; g++) s += u.part[g][r][d];
        out_o[((size_t)bh * QLEN + q0 + r) * DK + d] = s;
    }
}

extern "C" void kernel_launch(void* const* d_in, const int* in_sizes, int n_in,
                              void* d_out, int out_size)
{
    const float* q     = (const float*)d_in[0];
    const float* k     = (const float*)d_in[1];
    const float* v     = (const float*)d_in[2];
    const float* prev  = (const float*)d_in[3];
    const float* scale = (const float*)d_in[4];

    float* out_o = (float*)d_out;
    float* out_w = nullptr;
    float* out_s = nullptr;
    if (out_size >= FULL_OUT) {           // (output, attn_weights, attn_scores)
        out_w = out_o + O_ELEMS;
        out_s = out_w + W_ELEMS;
    }

    const int grid = BS * H * (QLEN / ROWS);   // 4096
    sdpa_kernel<<<grid, T>>>(q, k, v, prev, scale, out_o, out_w, out_s);
}

// round 3
// speedup vs baseline: 1.2459x; 1.1244x over previous
#include <cuda_runtime.h>

#define BS   2
#define H    16
#define QLEN 1024
#define SLEN 1024
#define DK   64
#define ROWS 16          // q rows per block
#define T    256         // threads per block (8 warps)
#define SSTR 1028        // padded score row stride (conflict-free frag loads)
#define QSTR 68          // padded q row stride

#define O_ELEMS  (BS*H*QLEN*DK)
#define W_ELEMS  (BS*H*QLEN*SLEN)
#define FULL_OUT (O_ELEMS + 2*W_ELEMS)

// smem (floats): S[16][1028] | union{ QH[16][68], QL[16][68] | RED[8][16][64] }
#define SM_S    0
#define SM_QH   (16*SSTR)
#define SM_QL   (SM_QH + 16*QSTR)
#define SM_RED  (16*SSTR)                  // overlaps QH/QL (dead by phase 3)
#define SM_FLOATS (16*SSTR + 8*16*64)      // 24640 floats = 98560 B

__device__ __forceinline__ unsigned f2tf(float x)
{
    unsigned r;
    asm("cvt.rna.tf32.f32 %0, %1;" : "=r"(r) : "f"(x));
    return r;
}

__device__ __forceinline__ void mma_tf32(float c[4],
                                         unsigned a0, unsigned a1, unsigned a2, unsigned a3,
                                         unsigned b0, unsigned b1)
{
    asm volatile(
        "mma.sync.aligned.m16n8k8.row.col.f32.tf32.tf32.f32 "
        "{%0,%1,%2,%3}, {%4,%5,%6,%7}, {%8,%9}, {%0,%1,%2,%3};"
        : "+f"(c[0]), "+f"(c[1]), "+f"(c[2]), "+f"(c[3])
        : "r"(a0), "r"(a1), "r"(a2), "r"(a3), "r"(b0), "r"(b1));
}

__global__ __launch_bounds__(T, 2)
void sdpa_kernel(const float* __restrict__ q,
                 const float* __restrict__ k,
                 const float* __restrict__ v,
                 const float* __restrict__ prev,
                 const float* __restrict__ scale_p,
                 float* __restrict__ out_o,
                 float* __restrict__ out_w,
                 float* __restrict__ out_s)
{
    extern __shared__ float sm[];
    float* S  = sm + SM_S;
    float* QH = sm + SM_QH;
    float* QL = sm + SM_QL;
    float* RED= sm + SM_RED;

    const int tid  = threadIdx.x;
    const int warp = tid >> 5;
    const int lane = tid & 31;
    const int g    = lane >> 2;       // groupID 0..7
    const int t    = lane & 3;        // threadID_in_group 0..3

    const int blk = blockIdx.x;
    const int bh  = blk >> 6;                    // 0..31
    const int q0  = (blk & 63) * ROWS;           // step 16

    const float scale = *scale_p;

    const float* qb = q    + ((size_t)bh * QLEN + q0) * DK;
    const float* kb = k    + (size_t)bh * DK * SLEN;
    const float* vb = v    + (size_t)bh * SLEN * DK;
    const float* pb = prev + ((size_t)bh * QLEN + q0) * SLEN;

    // ---- q split into tf32 hi/lo in smem ----
    for (int i = tid; i < ROWS * DK; i += T) {
        const int r = i >> 6, c = i & 63;
        const float x  = qb[i];
        const float hi = __uint_as_float(f2tf(x));
        QH[r * QSTR + c] = hi;
        QL[r * QSTR + c] = x - hi;
    }
    __syncthreads();

    // ================= phase 1: S = (Q @ K) * scale + prev =================
    // warp owns 128 columns; 2 chunks of 8 n-tiles; 8 k-tiles; 3xTF32.
    {
        const int nbase = warp * 128;
        #pragma unroll
        for (int chunk = 0; chunk < 2; chunk++) {
            float C[8][4];
            #pragma unroll
            for (int nt = 0; nt < 8; nt++)
                C[nt][0] = C[nt][1] = C[nt][2] = C[nt][3] = 0.f;

            const int ncol = nbase + chunk * 64;
            #pragma unroll
            for (int kk = 0; kk < 8; kk++) {
                const int kc = kk * 8 + t;
                const unsigned ah0 = __float_as_uint(QH[g * QSTR + kc]);
                const unsigned ah1 = __float_as_uint(QH[(g + 8) * QSTR + kc]);
                const unsigned ah2 = __float_as_uint(QH[g * QSTR + kc + 4]);
                const unsigned ah3 = __float_as_uint(QH[(g + 8) * QSTR + kc + 4]);
                const unsigned al0 = __float_as_uint(QL[g * QSTR + kc]);
                const unsigned al1 = __float_as_uint(QL[(g + 8) * QSTR + kc]);
                const unsigned al2 = __float_as_uint(QL[g * QSTR + kc + 4]);
                const unsigned al3 = __float_as_uint(QL[(g + 8) * QSTR + kc + 4]);

                const float* kr0 = kb + (size_t)(kk * 8 + t)     * SLEN + ncol + g;
                const float* kr1 = kb + (size_t)(kk * 8 + t + 4) * SLEN + ncol + g;
                #pragma unroll
                for (int nt = 0; nt < 8; nt++) {
                    const float b0f = kr0[nt * 8];
                    const float b1f = kr1[nt * 8];
                    const unsigned bh0 = f2tf(b0f);
                    const unsigned bh1 = f2tf(b1f);
                    const unsigned bl0 = __float_as_uint(b0f - __uint_as_float(bh0));
                    const unsigned bl1 = __float_as_uint(b1f - __uint_as_float(bh1));
                    mma_tf32(C[nt], ah0, ah1, ah2, ah3, bh0, bh1);
                    mma_tf32(C[nt], al0, al1, al2, al3, bh0, bh1);
                    mma_tf32(C[nt], ah0, ah1, ah2, ah3, bl0, bl1);
                }
            }

            // epilogue: *scale + prev, stash to smem + stream to out_s
            #pragma unroll
            for (int nt = 0; nt < 8; nt++) {
                const int n0 = ncol + nt * 8 + 2 * t;
                const float2 p0 = __ldcs((const float2*)(pb + (size_t)g       * SLEN + n0));
                const float2 p1 = __ldcs((const float2*)(pb + (size_t)(g + 8) * SLEN + n0));
                float2 s0, s1;
                s0.x = fmaf(C[nt][0], scale, p0.x);
                s0.y = fmaf(C[nt][1], scale, p0.y);
                s1.x = fmaf(C[nt][2], scale, p1.x);
                s1.y = fmaf(C[nt][3], scale, p1.y);
                *(float2*)&S[g * SSTR + n0]       = s0;
                *(float2*)&S[(g + 8) * SSTR + n0] = s1;
                if (out_s) {
                    __stcs((float2*)(out_s + ((size_t)bh * QLEN + q0 + g)     * SLEN + n0), s0);
                    __stcs((float2*)(out_s + ((size_t)bh * QLEN + q0 + g + 8) * SLEN + n0), s1);
                }
            }
        }
    }
    __syncthreads();

    // ================= phase 2: softmax (warp handles 2 rows) =================
    {
        #pragma unroll
        for (int rr = 0; rr < 2; rr++) {
            const int r = warp * 2 + rr;
            float* row = &S[r * SSTR];

            float mx = -1e30f;
            for (int i = lane; i < SLEN; i += 32)
                mx = fmaxf(mx, row[i]);
            #pragma unroll
            for (int o = 16; o > 0; o >>= 1)
                mx = fmaxf(mx, __shfl_xor_sync(0xffffffffu, mx, o));

            float sum = 0.f;
            for (int i = lane; i < SLEN; i += 32) {
                const float e = __expf(row[i] - mx);
                row[i] = e;
                sum += e;
            }
            #pragma unroll
            for (int o = 16; o > 0; o >>= 1)
                sum += __shfl_xor_sync(0xffffffffu, sum, o);

            const float inv = 1.0f / sum;
            float* wrow = out_w ? (out_w + ((size_t)bh * QLEN + q0 + r) * SLEN) : nullptr;
            for (int i = lane; i < SLEN; i += 32) {
                const float wv = row[i] * inv;
                row[i] = wv;
                if (wrow) __stcs(wrow + i, wv);
            }
        }
    }
    __syncthreads();

    // ================= phase 3: O = P @ V (split-k over warps) =================
    {
        float C[8][4];
        #pragma unroll
        for (int nt = 0; nt < 8; nt++)
            C[nt][0] = C[nt][1] = C[nt][2] = C[nt][3] = 0.f;

        const int sbase = warp * 128;
        #pragma unroll 4
        for (int kt = 0; kt < 16; kt++) {
            const int s0 = sbase + kt * 8;
            const float a0f = S[g * SSTR + s0 + t];
            const float a1f = S[(g + 8) * SSTR + s0 + t];
            const float a2f = S[g * SSTR + s0 + t + 4];
            const float a3f = S[(g + 8) * SSTR + s0 + t + 4];
            const unsigned ah0 = f2tf(a0f), ah1 = f2tf(a1f), ah2 = f2tf(a2f), ah3 = f2tf(a3f);
            const unsigned al0 = __float_as_uint(a0f - __uint_as_float(ah0));
            const unsigned al1 = __float_as_uint(a1f - __uint_as_float(ah1));
            const unsigned al2 = __float_as_uint(a2f - __uint_as_float(ah2));
            const unsigned al3 = __float_as_uint(a3f - __uint_as_float(ah3));

            const float* vr0 = vb + (size_t)(s0 + t)     * DK + g;
            const float* vr1 = vb + (size_t)(s0 + t + 4) * DK + g;
            #pragma unroll
            for (int nt = 0; nt < 8; nt++) {
                const float b0f = vr0[nt * 8];
                const float b1f = vr1[nt * 8];
                const unsigned bh0 = f2tf(b0f);
                const unsigned bh1 = f2tf(b1f);
                const unsigned bl0 = __float_as_uint(b0f - __uint_as_float(bh0));
                const unsigned bl1 = __float_as_uint(b1f - __uint_as_float(bh1));
                mma_tf32(C[nt], ah0, ah1, ah2, ah3, bh0, bh1);
                mma_tf32(C[nt], al0, al1, al2, al3, bh0, bh1);
                mma_tf32(C[nt], ah0, ah1, ah2, ah3, bl0, bl1);
            }
        }

        // partials -> smem
        #pragma unroll
        for (int nt = 0; nt < 8; nt++) {
            const int d0 = nt * 8 + 2 * t;
            *(float2*)&RED[(warp * 16 + g)     * 64 + d0] = make_float2(C[nt][0], C[nt][1]);
            *(float2*)&RED[(warp * 16 + g + 8) * 64 + d0] = make_float2(C[nt][2], C[nt][3]);
        }
    }
    __syncthreads();

    // cross-warp reduce + coalesced store
    for (int i = tid; i < ROWS * DK; i += T) {
        const int r = i >> 6, d = i & 63;
        float s = 0.f;
        #pragma unroll
        for (int w = 0; w < 8; w++) s += RED[(w * 16 + r) * 64 + d];
        out_o[((size_t)bh * QLEN + q0 + r) * DK + d] = s;
    }
}

extern "C" void kernel_launch(void* const* d_in, const int* in_sizes, int n_in,
                              void* d_out, int out_size)
{
    const float* q     = (const float*)d_in[0];
    const float* k     = (const float*)d_in[1];
    const float* v     = (const float*)d_in[2];
    const float* prev  = (const float*)d_in[3];
    const float* scale = (const float*)d_in[4];

    float* out_o = (float*)d_out;
    float* out_w = nullptr;
    float* out_s = nullptr;
    if (out_size >= FULL_OUT) {
        out_w = out_o + O_ELEMS;
        out_s = out_w + W_ELEMS;
    }

    const size_t smem = SM_FLOATS * sizeof(float);   // ~96 KB
    static bool attr_set = false;
    if (!attr_set) {
        cudaFuncSetAttribute(sdpa_kernel, cudaFuncAttributeMaxDynamicSharedMemorySize,
                             (int)smem);
        attr_set = true;
    }

    const int grid = BS * H * (QLEN / ROWS);   // 2048
    sdpa_kernel<<<grid, T, smem>>>(q, k, v, prev, scale, out_o, out_w, out_s);
}

// round 5
// speedup vs baseline: 1.2534x; 1.0060x over previous
#include <cuda_runtime.h>

#define BS   2
#define H    16
#define QLEN 1024
#define SLEN 1024
#define DK   64
#define ROWS 32          // q rows per block
#define T    512         // 16 warps
#define SSTR 1028        // padded score row stride
#define QSTR 68          // padded q row stride

#define O_ELEMS  (BS*H*QLEN*DK)
#define W_ELEMS  (BS*H*QLEN*SLEN)
#define FULL_OUT (O_ELEMS + 2*W_ELEMS)

// smem floats: S[32][1028] | QH[32][68] | QL[32][68]
// RED[8][32][64] (16384 floats) aliases the FRONT of S, and S is fully dead
// (all reads complete, barrier passed) before any RED write.
#define SM_S      0
#define SM_QH     (ROWS*SSTR)
#define SM_QL     (SM_QH + ROWS*QSTR)
#define SM_FLOATS (SM_QL + ROWS*QSTR)     // 37248 floats = 148992 B

__device__ __forceinline__ unsigned f2tf(float x)
{
    unsigned r;
    asm("cvt.rna.tf32.f32 %0, %1;" : "=r"(r) : "f"(x));
    return r;
}

__device__ __forceinline__ void mma_tf32(float c[4],
                                         unsigned a0, unsigned a1, unsigned a2, unsigned a3,
                                         unsigned b0, unsigned b1)
{
    asm volatile(
        "mma.sync.aligned.m16n8k8.row.col.f32.tf32.tf32.f32 "
        "{%0,%1,%2,%3}, {%4,%5,%6,%7}, {%8,%9}, {%0,%1,%2,%3};"
        : "+f"(c[0]), "+f"(c[1]), "+f"(c[2]), "+f"(c[3])
        : "r"(a0), "r"(a1), "r"(a2), "r"(a3), "r"(b0), "r"(b1));
}

__global__ __launch_bounds__(T, 1)
void sdpa_kernel(const float* __restrict__ q,
                 const float* __restrict__ k,
                 const float* __restrict__ v,
                 const float* __restrict__ prev,
                 const float* __restrict__ scale_p,
                 float* __restrict__ out_o,
                 float* __restrict__ out_w,
                 float* __restrict__ out_s)
{
    extern __shared__ float sm[];
    float* S   = sm + SM_S;
    float* QH  = sm + SM_QH;
    float* QL  = sm + SM_QL;
    float* RED = sm + SM_S;          // alias: valid only after S is globally dead

    const int tid  = threadIdx.x;
    const int warp = tid >> 5;
    const int lane = tid & 31;
    const int g    = lane >> 2;      // 0..7
    const int t    = lane & 3;       // 0..3

    const int blk = blockIdx.x;
    const int bh  = blk >> 5;                 // 0..31
    const int q0  = (blk & 31) * ROWS;        // step 32

    const float scale = *scale_p;

    const float* qb = q    + ((size_t)bh * QLEN + q0) * DK;
    const float* kb = k    + (size_t)bh * DK * SLEN;
    const float* vb = v    + (size_t)bh * SLEN * DK;
    const float* pb = prev + ((size_t)bh * QLEN + q0) * SLEN;

    // ---- q split into tf32 hi/lo in smem ----
    for (int i = tid; i < ROWS * DK; i += T) {
        const int r = i >> 6, c = i & 63;
        const float x  = qb[i];
        const float hi = __uint_as_float(f2tf(x));
        QH[r * QSTR + c] = hi;
        QL[r * QSTR + c] = x - hi;
    }
    __syncthreads();

    // ================= phase 1: S = (Q @ K) * scale + prev =================
    // warp owns 64 s-cols; 2 n-chunks of 4 tiles; 2 m-tiles (32 rows); 3xTF32
    {
        const int nbase = warp * 64;
        #pragma unroll
        for (int chunk = 0; chunk < 2; chunk++) {
            const int ncol = nbase + chunk * 32;
            float C[2][4][4];
            #pragma unroll
            for (int m = 0; m < 2; m++)
                #pragma unroll
                for (int nt = 0; nt < 4; nt++)
                    C[m][nt][0] = C[m][nt][1] = C[m][nt][2] = C[m][nt][3] = 0.f;

            #pragma unroll
            for (int kk = 0; kk < 8; kk++) {
                const int kc = kk * 8 + t;
                unsigned ah[2][4], al[2][4];
                #pragma unroll
                for (int m = 0; m < 2; m++) {
                    const int r0 = (m * 16 + g) * QSTR + kc;
                    const int r1 = (m * 16 + g + 8) * QSTR + kc;
                    ah[m][0] = __float_as_uint(QH[r0]);
                    ah[m][1] = __float_as_uint(QH[r1]);
                    ah[m][2] = __float_as_uint(QH[r0 + 4]);
                    ah[m][3] = __float_as_uint(QH[r1 + 4]);
                    al[m][0] = __float_as_uint(QL[r0]);
                    al[m][1] = __float_as_uint(QL[r1]);
                    al[m][2] = __float_as_uint(QL[r0 + 4]);
                    al[m][3] = __float_as_uint(QL[r1 + 4]);
                }
                const float* kr0 = kb + (size_t)(kk * 8 + t) * SLEN + ncol + g;
                const float* kr1 = kr0 + 4 * SLEN;
                #pragma unroll
                for (int nt = 0; nt < 4; nt++) {
                    const float b0f = kr0[nt * 8];
                    const float b1f = kr1[nt * 8];
                    const unsigned bh0 = f2tf(b0f);
                    const unsigned bh1 = f2tf(b1f);
                    const unsigned bl0 = __float_as_uint(b0f - __uint_as_float(bh0));
                    const unsigned bl1 = __float_as_uint(b1f - __uint_as_float(bh1));
                    #pragma unroll
                    for (int m = 0; m < 2; m++) {
                        mma_tf32(C[m][nt], ah[m][0], ah[m][1], ah[m][2], ah[m][3], bh0, bh1);
                        mma_tf32(C[m][nt], al[m][0], al[m][1], al[m][2], al[m][3], bh0, bh1);
                        mma_tf32(C[m][nt], ah[m][0], ah[m][1], ah[m][2], ah[m][3], bl0, bl1);
                    }
                }
            }

            // epilogue: *scale + prev -> smem S + stream out_s
            #pragma unroll
            for (int m = 0; m < 2; m++) {
                #pragma unroll
                for (int nt = 0; nt < 4; nt++) {
                    const int n0 = ncol + nt * 8 + 2 * t;
                    const int r0 = m * 16 + g;
                    const int r1 = r0 + 8;
                    const float2 p0 = __ldcs((const float2*)(pb + (size_t)r0 * SLEN + n0));
                    const float2 p1 = __ldcs((const float2*)(pb + (size_t)r1 * SLEN + n0));
                    float2 s0, s1;
                    s0.x = fmaf(C[m][nt][0], scale, p0.x);
                    s0.y = fmaf(C[m][nt][1], scale, p0.y);
                    s1.x = fmaf(C[m][nt][2], scale, p1.x);
                    s1.y = fmaf(C[m][nt][3], scale, p1.y);
                    *(float2*)&S[r0 * SSTR + n0] = s0;
                    *(float2*)&S[r1 * SSTR + n0] = s1;
                    if (out_s) {
                        __stcs((float2*)(out_s + ((size_t)bh * QLEN + q0 + r0) * SLEN + n0), s0);
                        __stcs((float2*)(out_s + ((size_t)bh * QLEN + q0 + r1) * SLEN + n0), s1);
                    }
                }
            }
        }
    }
    __syncthreads();

    // ================= phase 2: softmax (warp handles 2 rows, reg-resident) ==
    {
        #pragma unroll
        for (int rr = 0; rr < 2; rr++) {
            const int r = warp * 2 + rr;
            float* row = &S[r * SSTR];

            float4 vv[8];
            #pragma unroll
            for (int j = 0; j < 8; j++)
                vv[j] = *(const float4*)&row[(j * 32 + lane) * 4];

            float mx = -1e30f;
            #pragma unroll
            for (int j = 0; j < 8; j++)
                mx = fmaxf(mx, fmaxf(fmaxf(vv[j].x, vv[j].y), fmaxf(vv[j].z, vv[j].w)));
            #pragma unroll
            for (int o = 16; o > 0; o >>= 1)
                mx = fmaxf(mx, __shfl_xor_sync(0xffffffffu, mx, o));

            float sum = 0.f;
            #pragma unroll
            for (int j = 0; j < 8; j++) {
                vv[j].x = __expf(vv[j].x - mx);
                vv[j].y = __expf(vv[j].y - mx);
                vv[j].z = __expf(vv[j].z - mx);
                vv[j].w = __expf(vv[j].w - mx);
                sum += (vv[j].x + vv[j].y) + (vv[j].z + vv[j].w);
            }
            #pragma unroll
            for (int o = 16; o > 0; o >>= 1)
                sum += __shfl_xor_sync(0xffffffffu, sum, o);

            const float inv = 1.0f / sum;
            float* wrow = out_w ? (out_w + ((size_t)bh * QLEN + q0 + r) * SLEN) : nullptr;
            #pragma unroll
            for (int j = 0; j < 8; j++) {
                vv[j].x *= inv; vv[j].y *= inv; vv[j].z *= inv; vv[j].w *= inv;
                *(float4*)&row[(j * 32 + lane) * 4] = vv[j];
                if (wrow) __stcs((float4*)&wrow[(j * 32 + lane) * 4], vv[j]);
            }
        }
    }
    __syncthreads();

    // ================= phase 3: O = P @ V =================
    // warp = (m-tile = warp&1) x (s-group = warp>>1, 128 s each).
    // Full d=64 per warp (8 n-tiles). S is read ONLY in this loop; RED writes
    // happen strictly after the barrier below.
    {
        const int m  = warp & 1;
        const int sg = warp >> 1;
        const int sbase = sg * 128;

        float C[8][4];
        #pragma unroll
        for (int nt = 0; nt < 8; nt++)
            C[nt][0] = C[nt][1] = C[nt][2] = C[nt][3] = 0.f;

        #pragma unroll 4
        for (int kt = 0; kt < 16; kt++) {
            const int s0 = sbase + kt * 8;
            const int r0 = (m * 16 + g) * SSTR + s0 + t;
            const int r1 = (m * 16 + g + 8) * SSTR + s0 + t;
            const float a0f = S[r0], a1f = S[r1], a2f = S[r0 + 4], a3f = S[r1 + 4];
            const unsigned ah0 = f2tf(a0f), ah1 = f2tf(a1f), ah2 = f2tf(a2f), ah3 = f2tf(a3f);
            const unsigned al0 = __float_as_uint(a0f - __uint_as_float(ah0));
            const unsigned al1 = __float_as_uint(a1f - __uint_as_float(ah1));
            const unsigned al2 = __float_as_uint(a2f - __uint_as_float(ah2));
            const unsigned al3 = __float_as_uint(a3f - __uint_as_float(ah3));

            const float* vr0 = vb + (size_t)(s0 + t) * DK + g;
            const float* vr1 = vr0 + 4 * DK;
            #pragma unroll
            for (int nt = 0; nt < 8; nt++) {
                const float b0f = vr0[nt * 8];
                const float b1f = vr1[nt * 8];
                const unsigned bh0 = f2tf(b0f);
                const unsigned bh1 = f2tf(b1f);
                const unsigned bl0 = __float_as_uint(b0f - __uint_as_float(bh0));
                const unsigned bl1 = __float_as_uint(b1f - __uint_as_float(bh1));
                mma_tf32(C[nt], ah0, ah1, ah2, ah3, bh0, bh1);
                mma_tf32(C[nt], al0, al1, al2, al3, bh0, bh1);
                mma_tf32(C[nt], ah0, ah1, ah2, ah3, bl0, bl1);
            }
        }

        __syncthreads();   // ALL warps done reading S -> safe to overwrite with RED

        // partials -> RED[sg][32][64], 8*g column rotation (bank-conflict-free)
        {
            const int rot = 8 * g;
            #pragma unroll
            for (int nt = 0; nt < 8; nt++) {
                const int d0 = (nt * 8 + 2 * t + rot) & 63;
                const int r0 = m * 16 + g;
                const int r1 = r0 + 8;
                *(float2*)&RED[(sg * 32 + r0) * 64 + d0] = make_float2(C[nt][0], C[nt][1]);
                *(float2*)&RED[(sg * 32 + r1) * 64 + d0] = make_float2(C[nt][2], C[nt][3]);
            }
        }
    }
    __syncthreads();

    // reduce over 8 s-groups, un-rotate, coalesced float4 store
    // 32 rows * 16 float4 = 512 items = one per thread
    {
        const int r  = tid >> 4;          // 0..31
        const int dq = tid & 15;          // float4 index 0..15
        const int dqr = (dq + 2 * (r & 7)) & 15;   // un-rotate
        float4 acc = make_float4(0.f, 0.f, 0.f, 0.f);
        #pragma unroll
        for (int sg = 0; sg < 8; sg++) {
            const float4 p = *(const float4*)&RED[(sg * 32 + r) * 64 + dqr * 4];
            acc.x += p.x; acc.y += p.y; acc.z += p.z; acc.w += p.w;
        }
        *(float4*)(out_o + ((size_t)bh * QLEN + q0 + r) * DK + dq * 4) = acc;
    }
}

extern "C" void kernel_launch(void* const* d_in, const int* in_sizes, int n_in,
                              void* d_out, int out_size)
{
    const float* q     = (const float*)d_in[0];
    const float* k     = (const float*)d_in[1];
    const float* v     = (const float*)d_in[2];
    const float* prev  = (const float*)d_in[3];
    const float* scale = (const float*)d_in[4];

    float* out_o = (float*)d_out;
    float* out_w = nullptr;
    float* out_s = nullptr;
    if (out_size >= FULL_OUT) {
        out_w = out_o + O_ELEMS;
        out_s = out_w + W_ELEMS;
    }

    const size_t smem = SM_FLOATS * sizeof(float);   // ~146 KB
    static bool attr_set = false;
    if (!attr_set) {
        cudaFuncSetAttribute(sdpa_kernel, cudaFuncAttributeMaxDynamicSharedMemorySize,
                             (int)smem);
        attr_set = true;
    }

    const int grid = BS * H * (QLEN / ROWS);   // 1024
    sdpa_kernel<<<grid, T, smem>>>(q, k, v, prev, scale, out_o, out_w, out_s);
}

// round 6
// speedup vs baseline: 1.4314x; 1.1420x over previous
#include <cuda_runtime.h>

#define BS   2
#define H    16
#define QLEN 1024
#define SLEN 1024
#define DK   64
#define ROWS 32          // q rows per block
#define T    512         // 16 warps
#define SSTR 1032        // padded score row stride (floats), 1032%32=8
#define QS2  36          // packed-q row stride (uint32), 36%32=4

#define O_ELEMS  (BS*H*QLEN*DK)
#define W_ELEMS  (BS*H*QLEN*SLEN)
#define FULL_OUT (O_ELEMS + 2*W_ELEMS)

// smem floats: S[32][1032] | QH2[32][36](u32) | QL2[32][36](u32)
// RED[8][32][64] = 16384 floats aliases the FRONT of S; S fully dead first.
#define SM_S      0
#define SM_QH2    (ROWS*SSTR)
#define SM_QL2    (SM_QH2 + ROWS*QS2)
#define SM_FLOATS (SM_QL2 + ROWS*QS2)     // 35328 floats = 141312 B

__device__ __forceinline__ unsigned bfpack(float lo, float hi)
{
    unsigned r;
    asm("cvt.rn.bf16x2.f32 %0, %1, %2;" : "=r"(r) : "f"(hi), "f"(lo));
    return r;
}
__device__ __forceinline__ float blo(unsigned p) { return __uint_as_float(p << 16); }
__device__ __forceinline__ float bhi(unsigned p) { return __uint_as_float(p & 0xffff0000u); }

// split (x0,x1) into bf16 hi-pair and bf16 residual-pair
__device__ __forceinline__ void split2(float x0, float x1, unsigned& h, unsigned& l)
{
    h = bfpack(x0, x1);
    l = bfpack(x0 - blo(h), x1 - bhi(h));
}

__device__ __forceinline__ void mma_bf16(float c[4],
                                         unsigned a0, unsigned a1, unsigned a2, unsigned a3,
                                         unsigned b0, unsigned b1)
{
    asm volatile(
        "mma.sync.aligned.m16n8k16.row.col.f32.bf16.bf16.f32 "
        "{%0,%1,%2,%3}, {%4,%5,%6,%7}, {%8,%9}, {%0,%1,%2,%3};"
        : "+f"(c[0]), "+f"(c[1]), "+f"(c[2]), "+f"(c[3])
        : "r"(a0), "r"(a1), "r"(a2), "r"(a3), "r"(b0), "r"(b1));
}

__global__ __launch_bounds__(T, 1)
void sdpa_kernel(const float* __restrict__ q,
                 const float* __restrict__ k,
                 const float* __restrict__ v,
                 const float* __restrict__ prev,
                 const float* __restrict__ scale_p,
                 float* __restrict__ out_o,
                 float* __restrict__ out_w,
                 float* __restrict__ out_s)
{
    extern __shared__ float sm[];
    float*    S   = sm + SM_S;
    unsigned* QH2 = (unsigned*)(sm + SM_QH2);
    unsigned* QL2 = (unsigned*)(sm + SM_QL2);
    float*    RED = sm + SM_S;      // alias: valid only after S globally dead

    const int tid  = threadIdx.x;
    const int warp = tid >> 5;
    const int lane = tid & 31;
    const int g    = lane >> 2;     // 0..7
    const int t    = lane & 3;      // 0..3

    const int blk = blockIdx.x;
    const int bh  = blk >> 5;                 // 0..31
    const int q0  = (blk & 31) * ROWS;        // step 32

    const float scale = *scale_p;

    const float* qb = q    + ((size_t)bh * QLEN + q0) * DK;
    const float* kb = k    + (size_t)bh * DK * SLEN;
    const float* vb = v    + (size_t)bh * SLEN * DK;
    const float* pb = prev + ((size_t)bh * QLEN + q0) * SLEN;

    // ---- q: split into packed bf16 hi/lo pairs (d-pairs) in smem ----
    for (int i = tid; i < ROWS * 32; i += T) {
        const int r = i >> 5, c = i & 31;
        const float2 x = *(const float2*)(qb + r * DK + c * 2);
        unsigned h, l;
        split2(x.x, x.y, h, l);
        QH2[r * QS2 + c] = h;
        QL2[r * QS2 + c] = l;
    }
    __syncthreads();

    // ================= phase 1: rawS = Q @ K  (3x bf16, k16) ================
    // warp owns 64 s-cols; 2 n-chunks of 4 n-tiles; 2 m-tiles; 4 k-tiles(16).
    {
        const int nbase = warp * 64;
        #pragma unroll
        for (int chunk = 0; chunk < 2; chunk++) {
            const int ncol = nbase + chunk * 32;
            float C[2][4][4];
            #pragma unroll
            for (int m = 0; m < 2; m++)
                #pragma unroll
                for (int nt = 0; nt < 4; nt++)
                    C[m][nt][0] = C[m][nt][1] = C[m][nt][2] = C[m][nt][3] = 0.f;

            #pragma unroll
            for (int kk = 0; kk < 4; kk++) {
                unsigned ah[2][4], al[2][4];
                #pragma unroll
                for (int m = 0; m < 2; m++) {
                    const int r0 = (m * 16 + g) * QS2 + kk * 8 + t;
                    const int r1 = (m * 16 + g + 8) * QS2 + kk * 8 + t;
                    ah[m][0] = QH2[r0];     al[m][0] = QL2[r0];
                    ah[m][1] = QH2[r1];     al[m][1] = QL2[r1];
                    ah[m][2] = QH2[r0 + 4]; al[m][2] = QL2[r0 + 4];
                    ah[m][3] = QH2[r1 + 4]; al[m][3] = QL2[r1 + 4];
                }
                const float* kp = kb + (size_t)(kk * 16 + 2 * t) * SLEN + ncol + g;
                #pragma unroll
                for (int nt = 0; nt < 4; nt++) {
                    const float x0 = kp[nt * 8];
                    const float x1 = kp[SLEN + nt * 8];
                    const float x2 = kp[8 * SLEN + nt * 8];
                    const float x3 = kp[9 * SLEN + nt * 8];
                    unsigned bh0, bl0, bh1, bl1;
                    split2(x0, x1, bh0, bl0);
                    split2(x2, x3, bh1, bl1);
                    #pragma unroll
                    for (int m = 0; m < 2; m++) {
                        mma_bf16(C[m][nt], ah[m][0], ah[m][1], ah[m][2], ah[m][3], bh0, bh1);
                        mma_bf16(C[m][nt], al[m][0], al[m][1], al[m][2], al[m][3], bh0, bh1);
                        mma_bf16(C[m][nt], ah[m][0], ah[m][1], ah[m][2], ah[m][3], bl0, bl1);
                    }
                }
            }

            // raw qk -> smem only (scale/prev fused later, coalesced)
            #pragma unroll
            for (int m = 0; m < 2; m++) {
                #pragma unroll
                for (int nt = 0; nt < 4; nt++) {
                    const int n0 = ncol + nt * 8 + 2 * t;
                    const int r0 = m * 16 + g;
                    const int r1 = r0 + 8;
                    *(float2*)&S[r0 * SSTR + n0] = make_float2(C[m][nt][0], C[m][nt][1]);
                    *(float2*)&S[r1 * SSTR + n0] = make_float2(C[m][nt][2], C[m][nt][3]);
                }
            }
        }
    }
    __syncthreads();

    // ===== phase 2: s = qk*scale + prev; out_s; softmax; out_w (coalesced) ===
    {
        #pragma unroll
        for (int rr = 0; rr < 2; rr++) {
            const int r = warp * 2 + rr;
            float* row = &S[r * SSTR];
            const float* prow = pb + (size_t)r * SLEN;
            float* srow = out_s ? (out_s + ((size_t)bh * QLEN + q0 + r) * SLEN) : nullptr;
            float* wrow = out_w ? (out_w + ((size_t)bh * QLEN + q0 + r) * SLEN) : nullptr;

            float4 vv[8];
            float mx = -1e30f;
            #pragma unroll
            for (int j = 0; j < 8; j++) {
                const int idx = (j * 32 + lane) * 4;
                const float4 qk = *(const float4*)&row[idx];
                const float4 p4 = __ldcs((const float4*)(prow + idx));
                float4 s4;
                s4.x = fmaf(qk.x, scale, p4.x);
                s4.y = fmaf(qk.y, scale, p4.y);
                s4.z = fmaf(qk.z, scale, p4.z);
                s4.w = fmaf(qk.w, scale, p4.w);
                vv[j] = s4;
                if (srow) __stcs((float4*)(srow + idx), s4);
                mx = fmaxf(mx, fmaxf(fmaxf(s4.x, s4.y), fmaxf(s4.z, s4.w)));
            }
            #pragma unroll
            for (int o = 16; o > 0; o >>= 1)
                mx = fmaxf(mx, __shfl_xor_sync(0xffffffffu, mx, o));

            float sum = 0.f;
            #pragma unroll
            for (int j = 0; j < 8; j++) {
                vv[j].x = __expf(vv[j].x - mx);
                vv[j].y = __expf(vv[j].y - mx);
                vv[j].z = __expf(vv[j].z - mx);
                vv[j].w = __expf(vv[j].w - mx);
                sum += (vv[j].x + vv[j].y) + (vv[j].z + vv[j].w);
            }
            #pragma unroll
            for (int o = 16; o > 0; o >>= 1)
                sum += __shfl_xor_sync(0xffffffffu, sum, o);

            const float inv = 1.0f / sum;
            #pragma unroll
            for (int j = 0; j < 8; j++) {
                const int idx = (j * 32 + lane) * 4;
                vv[j].x *= inv; vv[j].y *= inv; vv[j].z *= inv; vv[j].w *= inv;
                *(float4*)&row[idx] = vv[j];
                if (wrow) __stcs((float4*)(wrow + idx), vv[j]);
            }
        }
    }
    __syncthreads();

    // ================= phase 3: O = P @ V (3x bf16, k16) ====================
    // warp = (m-tile = warp&1) x (s-group = warp>>1, 128 s each), full d=64.
    {
        const int m  = warp & 1;
        const int sg = warp >> 1;
        const int sbase = sg * 128;

        float C[8][4];
        #pragma unroll
        for (int nt = 0; nt < 8; nt++)
            C[nt][0] = C[nt][1] = C[nt][2] = C[nt][3] = 0.f;

        #pragma unroll 2
        for (int kt = 0; kt < 8; kt++) {
            const int s0 = sbase + kt * 16;
            const int r0f = (m * 16 + g) * SSTR + s0 + 2 * t;
            const int r1f = (m * 16 + g + 8) * SSTR + s0 + 2 * t;
            const float2 w00 = *(const float2*)&S[r0f];       // a0: rows g,   k 2t,2t+1
            const float2 w10 = *(const float2*)&S[r1f];       // a1: rows g+8
            const float2 w01 = *(const float2*)&S[r0f + 8];   // a2: k 2t+8,2t+9
            const float2 w11 = *(const float2*)&S[r1f + 8];   // a3
            unsigned ah0, al0, ah1, al1, ah2, al2, ah3, al3;
            split2(w00.x, w00.y, ah0, al0);
            split2(w10.x, w10.y, ah1, al1);
            split2(w01.x, w01.y, ah2, al2);
            split2(w11.x, w11.y, ah3, al3);

            const float* vp = vb + (size_t)(s0 + 2 * t) * DK + g;
            #pragma unroll
            for (int nt = 0; nt < 8; nt++) {
                const float x0 = vp[nt * 8];
                const float x1 = vp[DK + nt * 8];
                const float x2 = vp[8 * DK + nt * 8];
                const float x3 = vp[9 * DK + nt * 8];
                unsigned bh0, bl0, bh1, bl1;
                split2(x0, x1, bh0, bl0);
                split2(x2, x3, bh1, bl1);
                mma_bf16(C[nt], ah0, ah1, ah2, ah3, bh0, bh1);
                mma_bf16(C[nt], al0, al1, al2, al3, bh0, bh1);
                mma_bf16(C[nt], ah0, ah1, ah2, ah3, bl0, bl1);
            }
        }

        __syncthreads();   // all warps done reading S -> safe to alias as RED

        // partials -> RED[sg][32][64], 8*g column rotation (conflict-free)
        {
            const int rot = 8 * g;
            #pragma unroll
            for (int nt = 0; nt < 8; nt++) {
                const int d0 = (nt * 8 + 2 * t + rot) & 63;
                const int r0 = m * 16 + g;
                const int r1 = r0 + 8;
                *(float2*)&RED[(sg * 32 + r0) * 64 + d0] = make_float2(C[nt][0], C[nt][1]);
                *(float2*)&RED[(sg * 32 + r1) * 64 + d0] = make_float2(C[nt][2], C[nt][3]);
            }
        }
    }
    __syncthreads();

    // reduce over 8 s-groups, un-rotate, coalesced float4 store
    {
        const int r  = tid >> 4;                    // 0..31
        const int dq = tid & 15;                    // float4 idx 0..15
        const int dqr = (dq + 2 * (r & 7)) & 15;    // un-rotate
        float4 acc = make_float4(0.f, 0.f, 0.f, 0.f);
        #pragma unroll
        for (int sg = 0; sg < 8; sg++) {
            const float4 p = *(const float4*)&RED[(sg * 32 + r) * 64 + dqr * 4];
            acc.x += p.x; acc.y += p.y; acc.z += p.z; acc.w += p.w;
        }
        *(float4*)(out_o + ((size_t)bh * QLEN + q0 + r) * DK + dq * 4) = acc;
    }
}

extern "C" void kernel_launch(void* const* d_in, const int* in_sizes, int n_in,
                              void* d_out, int out_size)
{
    const float* q     = (const float*)d_in[0];
    const float* k     = (const float*)d_in[1];
    const float* v     = (const float*)d_in[2];
    const float* prev  = (const float*)d_in[3];
    const float* scale = (const float*)d_in[4];

    float* out_o = (float*)d_out;
    float* out_w = nullptr;
    float* out_s = nullptr;
    if (out_size >= FULL_OUT) {
        out_w = out_o + O_ELEMS;
        out_s = out_w + W_ELEMS;
    }

    const size_t smem = SM_FLOATS * sizeof(float);   // ~138 KB
    static bool attr_set = false;
    if (!attr_set) {
        cudaFuncSetAttribute(sdpa_kernel, cudaFuncAttributeMaxDynamicSharedMemorySize,
                             (int)smem);
        attr_set = true;
    }

    const int grid = BS * H * (QLEN / ROWS);   // 1024
    sdpa_kernel<<<grid, T, smem>>>(q, k, v, prev, scale, out_o, out_w, out_s);
}